// round 5
// baseline (speedup 1.0000x reference)
#include <cuda_runtime.h>

#define TPB     256
#define NBINS   64
#define SBINS   56            // max bin = ceil(31.5*sqrt(3)) = 55
#define HSTRIDE 258           // u16 per-bin stride: 516B = 129 words (odd)
#define HWORDS  (SBINS * HSTRIDE / 2)   // 7224 u32 words = 28,896 B
#define NPTS    4096
#define NGRP    1024          // NPTS / 4
#define NSTRIP  1024          // 4-row strips
#define GRID    512           // one unit (strips s and 1023-s) per block

// Scratch (allocation-free __device__ globals). Zero at entry of every
// launch; the finalizing block resets them (graph-replay safe).
__device__ int      g_hist[NBINS];
__device__ unsigned g_done = 0;

__device__ __forceinline__ int pair_bin(float dx, float dy, float dz) {
    const float s = dx * dx + dy * dy + dz * dz;     // FMA ok (tol 1e-3)
    float r;
    // ceil(31.5*sqrt(s)) == ceil(sqrt(992.25*s));  sqrt.approx(0)=0 -> bin 0
    asm("sqrt.approx.f32 %0, %1;" : "=f"(r) : "f"(992.25f * s));
    return min(__float2int_ru(r), SBINS - 1);
}

__global__ __launch_bounds__(TPB, 4)
void ecc_kernel(const float* __restrict__ x, float* __restrict__ out, int n) {
    __shared__ unsigned short sh[SBINS * HSTRIDE];

    const int tid = threadIdx.x;
    unsigned* h32 = (unsigned*)sh;
    for (int k = tid; k < HWORDS; k += TPB) h32[k] = 0u;
    __syncthreads();

    unsigned short* myh = sh + tid;   // per-thread column
    const float4* __restrict__ x4 = (const float4*)x;

    int strips[2];
    strips[0] = (int)blockIdx.x;
    strips[1] = NSTRIP - 1 - (int)blockIdx.x;

    #pragma unroll
    for (int ss = 0; ss < 2; ss++) {
        const int s = strips[ss];

        // 4 strip points (rows 4s..4s+3) into registers: exactly 3 float4s
        const float4 A = __ldg(&x4[3 * s + 0]);
        const float4 B = __ldg(&x4[3 * s + 1]);
        const float4 C = __ldg(&x4[3 * s + 2]);
        const float p0x = A.x, p0y = A.y, p0z = A.z;
        const float p1x = A.w, p1y = B.x, p1z = B.y;
        const float p2x = B.z, p2y = B.w, p2z = C.x;
        const float p3x = C.y, p3y = C.z, p3z = C.w;

        // 6 intra-strip corner pairs: threads 0..5, scalar loads
        if (tid < 6) {
            const int ii = tid < 3 ? 0 : (tid < 5 ? 1 : 2);
            const int jj = tid < 3 ? tid + 1 : (tid < 5 ? tid - 2 : 3);
            const int i = 4 * s + ii, j = 4 * s + jj;
            const int b = pair_bin(__ldg(&x[3*i+0]) - __ldg(&x[3*j+0]),
                                   __ldg(&x[3*i+1]) - __ldg(&x[3*j+1]),
                                   __ldg(&x[3*i+2]) - __ldg(&x[3*j+2]));
            myh[b * HSTRIDE] += 1;
        }

        // j-groups [s+1, 1024): 3 LDG.128 -> 4 j points -> 16 pairs
        for (int g = s + 1 + tid; g < NGRP; g += TPB) {
            const float4 a = __ldg(&x4[3 * g + 0]);
            const float4 b = __ldg(&x4[3 * g + 1]);
            const float4 c = __ldg(&x4[3 * g + 2]);

            const int b00 = pair_bin(p0x - a.x, p0y - a.y, p0z - a.z);
            const int b10 = pair_bin(p1x - a.x, p1y - a.y, p1z - a.z);
            const int b20 = pair_bin(p2x - a.x, p2y - a.y, p2z - a.z);
            const int b30 = pair_bin(p3x - a.x, p3y - a.y, p3z - a.z);
            myh[b00 * HSTRIDE] += 1;
            myh[b10 * HSTRIDE] += 1;
            myh[b20 * HSTRIDE] += 1;
            myh[b30 * HSTRIDE] += 1;

            const int b01 = pair_bin(p0x - a.w, p0y - b.x, p0z - b.y);
            const int b11 = pair_bin(p1x - a.w, p1y - b.x, p1z - b.y);
            const int b21 = pair_bin(p2x - a.w, p2y - b.x, p2z - b.y);
            const int b31 = pair_bin(p3x - a.w, p3y - b.x, p3z - b.y);
            myh[b01 * HSTRIDE] += 1;
            myh[b11 * HSTRIDE] += 1;
            myh[b21 * HSTRIDE] += 1;
            myh[b31 * HSTRIDE] += 1;

            const int b02 = pair_bin(p0x - b.z, p0y - b.w, p0z - c.x);
            const int b12 = pair_bin(p1x - b.z, p1y - b.w, p1z - c.x);
            const int b22 = pair_bin(p2x - b.z, p2y - b.w, p2z - c.x);
            const int b32 = pair_bin(p3x - b.z, p3y - b.w, p3z - c.x);
            myh[b02 * HSTRIDE] += 1;
            myh[b12 * HSTRIDE] += 1;
            myh[b22 * HSTRIDE] += 1;
            myh[b32 * HSTRIDE] += 1;

            const int b03 = pair_bin(p0x - c.y, p0y - c.z, p0z - c.w);
            const int b13 = pair_bin(p1x - c.y, p1y - c.z, p1z - c.w);
            const int b23 = pair_bin(p2x - c.y, p2y - c.z, p2z - c.w);
            const int b33 = pair_bin(p3x - c.y, p3y - c.z, p3z - c.w);
            myh[b03 * HSTRIDE] += 1;
            myh[b13 * HSTRIDE] += 1;
            myh[b23 * HSTRIDE] += 1;
            myh[b33 * HSTRIDE] += 1;
        }
    }
    __syncthreads();

    // Reduce [56][129 words] -> g_hist: 4 threads/bin, stride-4 interleave
    if (tid < SBINS * 4) {
        const int b = tid >> 2;
        const int q = tid & 3;
        const unsigned* hb = h32 + b * (HSTRIDE / 2);  // 129 words per bin
        unsigned sum = 0;
        #pragma unroll
        for (int k = 0; k < 33; k++) {
            const int w = q + 4 * k;
            if (w < HSTRIDE / 2) {
                const unsigned v = hb[w];
                sum += (v & 0xFFFFu) + (v >> 16);
            }
        }
        sum += __shfl_xor_sync(0xffffffffu, sum, 1);
        sum += __shfl_xor_sync(0xffffffffu, sum, 2);
        if (q == 0) atomicAdd(&g_hist[b], (int)sum);
    }
    __syncthreads();

    // Last-done block: 64-bin scan, write out, reset scratch
    __shared__ unsigned s_last;
    if (tid == 0) {
        __threadfence();
        s_last = (atomicAdd(&g_done, 1u) == (unsigned)gridDim.x - 1u);
    }
    __syncthreads();
    if (s_last && tid == 0) {
        float acc = 0.0f;
        #pragma unroll
        for (int k = 0; k < NBINS; k++) {
            const int h = atomicAdd(&g_hist[k], 0);   // coherent read
            float v = -(float)h;
            if (k == 0) v += (float)n;                // +n vertices at filt 0
            acc += v;
            out[k] = acc;
            g_hist[k] = 0;
        }
        g_done = 0;
    }
}

extern "C" void kernel_launch(void* const* d_in, const int* in_sizes, int n_in,
                              void* d_out, int out_size) {
    const float* x = (const float*)d_in[0];
    float* out = (float*)d_out;
    const int n = in_sizes[0] / 3;   // 4096
    ecc_kernel<<<GRID, TPB>>>(x, out, n);
}

// round 6
// speedup vs baseline: 1.0406x; 1.0406x over previous
#include <cuda_runtime.h>

#define TPB    256
#define NBINS  64
#define SBINS  56          // max reachable bin = ceil(31.5*sqrt(3)) = 55
#define GRID   444         // 148 SMs * 3 CTAs/SM -> single wave
#define NUNITS 2048        // row-pairs (u, n-1-u): each exactly 4095 pairs

// Scratch (allocation-free __device__ globals). Zero at entry of every
// launch; the finalizing block resets them (graph-replay safe).
__device__ int      g_hist[NBINS];
__device__ unsigned g_done = 0;

__global__ __launch_bounds__(TPB, 3)
void ecc_kernel(const float* __restrict__ x, float* __restrict__ out, int n) {
    __shared__ unsigned sh[SBINS * TPB];   // [bin][256]: column tid -> bank tid%32

    const int tid = threadIdx.x;
    unsigned* myh = sh + tid;

    #pragma unroll
    for (int k = 0; k < SBINS; k++) myh[k * TPB] = 0u;
    __syncthreads();

    // Units (u, n-1-u): 4095 pairs each; blocks 0-271 run 5 units, rest 4.
    for (int u = blockIdx.x; u < NUNITS; u += GRID) {
        int rows[2];
        rows[0] = u;
        rows[1] = n - 1 - u;
        #pragma unroll
        for (int rr = 0; rr < 2; rr++) {
            const int i = rows[rr];
            const float pix = __ldg(&x[3 * i + 0]);
            const float piy = __ldg(&x[3 * i + 1]);
            const float piz = __ldg(&x[3 * i + 2]);
            #pragma unroll 4
            for (int j = i + 1 + tid; j < n; j += TPB) {
                const float dx = pix - __ldg(&x[3 * j + 0]);
                const float dy = piy - __ldg(&x[3 * j + 1]);
                const float dz = piz - __ldg(&x[3 * j + 2]);
                const float s  = dx * dx + dy * dy + dz * dz;  // FMA ok (tol 1e-3)
                float r;
                // ceil(31.5*sqrt(s)) == ceil(sqrt(992.25*s)); approx err ~1e-7 rel
                asm("sqrt.approx.f32 %0, %1;" : "=f"(r) : "f"(992.25f * s));
                int b = __float2int_ru(r);     // s==0 -> r==0 -> bin 0 (= ref)
                b = min(b, SBINS - 1);
                myh[b * TPB] += 1u;            // conflict-free private column
            }
        }
    }
    __syncthreads();

    // Block-reduce [56][256] -> g_hist: 4 threads/bin, rotated (conflict-free)
    if (tid < SBINS * 4) {
        const int b = tid >> 2;
        const int q = tid & 3;
        unsigned sum = 0;
        #pragma unroll 8
        for (int c = 0; c < 64; c++)
            sum += sh[b * TPB + q * 64 + ((c + tid) & 63)];
        sum += __shfl_xor_sync(0xffffffffu, sum, 1);
        sum += __shfl_xor_sync(0xffffffffu, sum, 2);
        if (q == 0) atomicAdd(&g_hist[b], (int)sum);
    }
    __syncthreads();

    // Last-done block: 64-bin scan, write out, reset scratch
    __shared__ unsigned s_last;
    if (tid == 0) {
        __threadfence();
        s_last = (atomicAdd(&g_done, 1u) == (unsigned)gridDim.x - 1u);
    }
    __syncthreads();
    if (s_last && tid == 0) {
        float acc = 0.0f;
        #pragma unroll
        for (int k = 0; k < NBINS; k++) {
            const int h = atomicAdd(&g_hist[k], 0);   // coherent read
            float v = -(float)h;
            if (k == 0) v += (float)n;                // +n vertices at filt 0
            acc += v;
            out[k] = acc;
            g_hist[k] = 0;
        }
        g_done = 0;
    }
}

extern "C" void kernel_launch(void* const* d_in, const int* in_sizes, int n_in,
                              void* d_out, int out_size) {
    const float* x = (const float*)d_in[0];
    float* out = (float*)d_out;
    const int n = in_sizes[0] / 3;   // 4096
    ecc_kernel<<<GRID, TPB>>>(x, out, n);
}

// round 7
// speedup vs baseline: 1.9969x; 1.9190x over previous
#include <cuda_runtime.h>

#define TPB     256
#define NBINS   64
#define SBINS   56           // max bin = ceil(31.5*sqrt(3)) = 55
#define CPS     7            // CTAs per SM
#define GRID    (148 * CPS)  // 1036 blocks, single wave
#define NUNITS  2048         // row-pairs (u, n-1-u): each exactly 4095 pairs

// Scratch (allocation-free __device__ globals). Zero at entry of every
// launch; the finalizing block resets them (graph-replay safe).
__device__ int      g_hist[NBINS];
__device__ unsigned g_done = 0;
__device__ unsigned g_unit = 0;

__global__ __launch_bounds__(TPB, CPS)
void ecc_kernel(const float* __restrict__ x, float* __restrict__ out, int n) {
    // u16 hist [56][256]: column tid -> byte 2*tid + 512*bin.
    // bank = tid/2 for ANY bin pattern -> strictly conflict-free RMW.
    __shared__ unsigned short sh[SBINS * TPB];
    __shared__ int      s_u;
    __shared__ float    s_wsum;
    __shared__ unsigned s_last;

    const int tid = threadIdx.x;
    unsigned* h32 = (unsigned*)sh;
    #pragma unroll
    for (int k = tid; k < SBINS * TPB / 2; k += TPB) h32[k] = 0u;

    unsigned short* myh = sh + tid;

    // Dynamic work queue over uniform units (near-perfect balance)
    for (;;) {
        if (tid == 0) s_u = (int)atomicAdd(&g_unit, 1u);
        __syncthreads();                       // also covers zero-init (1st iter)
        const int u = s_u;
        if (u >= NUNITS) break;

        int rows[2];
        rows[0] = u;
        rows[1] = n - 1 - u;
        #pragma unroll
        for (int rr = 0; rr < 2; rr++) {
            const int i = rows[rr];
            const float pix = __ldg(&x[3 * i + 0]);
            const float piy = __ldg(&x[3 * i + 1]);
            const float piz = __ldg(&x[3 * i + 2]);
            #pragma unroll 4
            for (int j = i + 1 + tid; j < n; j += TPB) {
                const float dx = pix - __ldg(&x[3 * j + 0]);
                const float dy = piy - __ldg(&x[3 * j + 1]);
                const float dz = piz - __ldg(&x[3 * j + 2]);
                const float s  = dx * dx + dy * dy + dz * dz;  // FMA ok (tol 1e-3)
                float r;
                // ceil(31.5*sqrt(s)) == ceil(sqrt(992.25*s)); approx ok at tol
                asm("sqrt.approx.f32 %0, %1;" : "=f"(r) : "f"(992.25f * s));
                int b = __float2int_ru(r);     // s==0 -> 0 -> bin 0 (= ref)
                b = min(b, SBINS - 1);
                myh[b * TPB] += 1;             // u16 RMW, conflict-free
            }
        }
        __syncthreads();                       // protect s_u for next fetch
    }
    __syncthreads();                           // RMWs visible to reducers

    // Block-reduce [56][128 words] -> g_hist: 4 threads/bin, rotated banks
    if (tid < SBINS * 4) {
        const int b = tid >> 2;
        const int q = tid & 3;
        const unsigned* hb = h32 + b * 128;
        unsigned sum = 0;
        #pragma unroll
        for (int k = 0; k < 32; k++) {
            const unsigned v = hb[q * 32 + ((k + tid) & 31)];
            sum += (v & 0xFFFFu) + (v >> 16);
        }
        sum += __shfl_xor_sync(0xffffffffu, sum, 1);
        sum += __shfl_xor_sync(0xffffffffu, sum, 2);
        if (q == 0 && sum) atomicAdd(&g_hist[b], (int)sum);
    }
    __syncthreads();

    // Last-done block: PARALLEL 64-bin read + 2-warp shfl scan (no serial chain)
    if (tid == 0) {
        __threadfence();
        s_last = (atomicAdd(&g_done, 1u) == (unsigned)GRID - 1u);
    }
    __syncthreads();
    if (s_last) {
        float v = 0.0f;
        if (tid < NBINS) {
            const int h = atomicAdd(&g_hist[tid], 0);   // 64 parallel reads
            v = -(float)h;
            if (tid == 0) v += (float)n;                // +n vertices at filt 0
            #pragma unroll
            for (int d = 1; d < 32; d <<= 1) {          // inclusive warp scan
                const float t = __shfl_up_sync(0xffffffffu, v, d);
                if ((tid & 31) >= d) v += t;
            }
            if (tid == 31) s_wsum = v;                  // warp0 total
        }
        __syncthreads();
        if (tid < NBINS) {
            if (tid >= 32) v += s_wsum;
            out[tid] = v;
            g_hist[tid] = 0;                            // reset for next replay
        }
        if (tid == 0) { g_unit = 0; g_done = 0; }
    }
}

extern "C" void kernel_launch(void* const* d_in, const int* in_sizes, int n_in,
                              void* d_out, int out_size) {
    const float* x = (const float*)d_in[0];
    float* out = (float*)d_out;
    const int n = in_sizes[0] / 3;   // 4096
    ecc_kernel<<<GRID, TPB>>>(x, out, n);
}